// round 9
// baseline (speedup 1.0000x reference)
#include <cuda_runtime.h>

typedef unsigned long long ull;

#define NT 192
#define NSTEPS 16
#define DT (1.0f/16.0f)
// upper-triangle index for i<j, 8x8
#define TRI(i,j) ((i)*7 - (i)*((i)-1)/2 + (j) - (i) - 1)

__device__ __forceinline__ ull fma2(ull a, ull b, ull c){
    ull d; asm("fma.rn.f32x2 %0,%1,%2,%3;" : "=l"(d) : "l"(a),"l"(b),"l"(c)); return d;
}
__device__ __forceinline__ ull mul2(ull a, ull b){
    ull d; asm("mul.rn.f32x2 %0,%1,%2;" : "=l"(d) : "l"(a),"l"(b)); return d;
}
__device__ __forceinline__ ull add2(ull a, ull b){
    ull d; asm("add.rn.f32x2 %0,%1,%2;" : "=l"(d) : "l"(a),"l"(b)); return d;
}
__device__ __forceinline__ ull sub2(ull a, ull b){
    ull d; asm("sub.rn.f32x2 %0,%1,%2;" : "=l"(d) : "l"(a),"l"(b)); return d;
}
__device__ __forceinline__ float hsum2(ull a){
    float lo,hi; asm("mov.b64 {%0,%1},%2;" : "=f"(lo),"=f"(hi) : "l"(a)); return lo+hi;
}
__device__ __forceinline__ ull dup_f(float x){
    ull r; asm("mov.b64 %0,{%1,%1};" : "=l"(r) : "f"(x)); return r;
}
__device__ __forceinline__ ull dup_lo(ull a){
    ull r; asm("{.reg .f32 l,h; mov.b64 {l,h},%1; mov.b64 %0,{l,l};}" : "=l"(r) : "l"(a)); return r;
}
__device__ __forceinline__ ull dup_hi(ull a){
    ull r; asm("{.reg .f32 l,h; mov.b64 {l,h},%1; mov.b64 %0,{h,h};}" : "=l"(r) : "l"(a)); return r;
}
__device__ __forceinline__ ull pack2(float lo, float hi){
    ull r; asm("mov.b64 %0,{%1,%2};" : "=l"(r) : "f"(lo),"f"(hi)); return r;
}
__device__ __forceinline__ void unp2(ull a, float& lo, float& hi){
    asm("mov.b64 {%0,%1},%2;" : "=f"(lo),"=f"(hi) : "l"(a));
}
// packed dot of two 8-float rows (4 ull each): returns packed partial sums
__device__ __forceinline__ ull dotp(const ull* a, const ull* b){
    ull s = mul2(a[0],b[0]);
    s = fma2(a[1],b[1],s);
    s = fma2(a[2],b[2],s);
    s = fma2(a[3],b[3],s);
    return s;
}

extern "C" __global__ void __launch_bounds__(NT, 1)
adj_lie_kernel(const float* __restrict__ U0, const float* __restrict__ eps,
               const float* __restrict__ W0, const float* __restrict__ W1,
               const float* __restrict__ W2, float* __restrict__ out, int B)
{
    extern __shared__ ull shl[];
    ull* w2c  = shl;            // 32 : W2 column-packed: w2c[k*4+c] = (W2[2c][k], W2[2c+1][k])
    ull* w01  = shl + 32;       // 28 : (w0a_ij, w1a_ij) per TRI pair
    ull* svb  = shl + 64;               // [32][NT] : v (eps) rows packed
    ull* sgvb = svb  + 32*NT;           // [32][NT] : gv_j = W2 v_j^T rows packed
    ull* subb = sgvb + 32*NT;           // [32][NT] : U base
    ull* sacb = subb + 32*NT;           // [32][NT] : RK4 accumulator

    const int tid  = threadIdx.x;
    const int gtid = blockIdx.x * NT + tid;

    if (tid < 32) {
        int k = tid >> 2, c = tid & 3;
        w2c[tid] = pack2(W2[(2*c)*8 + k], W2[(2*c+1)*8 + k]);
    }
    if (tid < 64) {
        int i = tid >> 3, j = tid & 7;
        if (i < j) {
            w01[TRI(i,j)] = pack2(0.5f * (W0[i*8+j] - W0[j*8+i]),
                                  0.5f * (W1[i*8+j] - W1[j*8+i]));
        }
    }
    __syncthreads();

    if (gtid >= B) return;

    ull* sv  = svb  + tid;
    ull* sgv = sgvb + tid;
    ull* sub = subb + tid;
    ull* sac = sacb + tid;

    // ---- load U0 (regs + shared base) ----
    ull UeP[32];
    {
        const ulonglong2* u2 = (const ulonglong2*)(U0 + (size_t)gtid * 64);
        #pragma unroll
        for (int e = 0; e < 16; e++) {
            ulonglong2 u = u2[e];
            UeP[2*e] = u.x; UeP[2*e+1] = u.y;
        }
        #pragma unroll
        for (int c = 0; c < 32; c++) sub[c*NT] = UeP[c];
    }

    // ---- load eps: store v rows, and gv_j = W2 v_j^T (constant over integration) ----
    {
        const ulonglong2* e2 = (const ulonglong2*)(eps + (size_t)gtid * 64);
        #pragma unroll
        for (int j = 0; j < 8; j++) {
            ulonglong2 a = e2[2*j], b = e2[2*j+1];
            ull vr[4] = {a.x, a.y, b.x, b.y};
            #pragma unroll
            for (int c = 0; c < 4; c++) sv[(j*4+c)*NT] = vr[c];
            ull acc[4];
            #pragma unroll
            for (int k = 0; k < 8; k++) {
                ull d = (k & 1) ? dup_hi(vr[k>>1]) : dup_lo(vr[k>>1]);
                #pragma unroll
                for (int c = 0; c < 4; c++)
                    acc[c] = (k == 0) ? mul2(d, w2c[c]) : fma2(d, w2c[k*4+c], acc[c]);
            }
            #pragma unroll
            for (int c = 0; c < 4; c++) sgv[(j*4+c)*NT] = acc[c];
        }
    }

    float logj = 0.0f, lacc = 0.0f;

    #pragma unroll 1
    for (int step = 0; step < NSTEPS; step++) {
        float t0 = (float)step * DT;
        #pragma unroll 1
        for (int s = 0; s < 4; s++) {
            float t = t0 + ((s == 0) ? 0.0f : (s == 3 ? DT : 0.5f*DT));

            float kl;
            float fv[28];
            ull T[32];   // phase 1: G_j = W2*Ue_j^T ; phase 2: vel rows (in-place reuse)

            // ===== phase 1a: T = G  =====
            #pragma unroll
            for (int j = 0; j < 8; j++) {
                #pragma unroll
                for (int k = 0; k < 8; k++) {
                    ull d = (k & 1) ? dup_hi(UeP[j*4+(k>>1)]) : dup_lo(UeP[j*4+(k>>1)]);
                    #pragma unroll
                    for (int c = 0; c < 4; c++)
                        T[j*4+c] = (k == 0) ? mul2(d, w2c[c])
                                            : fma2(d, w2c[k*4+c], T[j*4+c]);
                }
            }

            // ===== phase 1b: fused pair loop: r, s1, s2, f =====
            {
                ull s1p = 0ull, s2p = 0ull;
                #pragma unroll
                for (int i = 0; i < 7; i++) {
                    ull vi[4], gvi[4];
                    #pragma unroll
                    for (int c = 0; c < 4; c++) { vi[c] = sv[(i*4+c)*NT]; gvi[c] = sgv[(i*4+c)*NT]; }
                    #pragma unroll
                    for (int j = i+1; j < 8; j++) {
                        ull vj[4], gvj[4];
                        #pragma unroll
                        for (int c = 0; c < 4; c++) { vj[c] = sv[(j*4+c)*NT]; gvj[c] = sgv[(j*4+c)*NT]; }

                        // r = <Ue_j, v_i> - <Ue_i, v_j>  (unscaled)
                        ull pr = sub2(dotp(&UeP[j*4], vi), dotp(&UeP[i*4], vj));
                        float r = hsum2(pr);
                        ull rd = dup_f(r);
                        // s1 += r * (<G_j, v_i> - <G_i, v_j>)
                        s1p = fma2(rd, sub2(dotp(&T[j*4], vi), dotp(&T[i*4], vj)), s1p);
                        // s2 += r * (<Ue_i, gv_j> - <Ue_j, gv_i>)
                        s2p = fma2(rd, sub2(dotp(&UeP[i*4], gvj), dotp(&UeP[j*4], gvi)), s2p);
                        // f = 0.5*(M[i][j]-M[j][i]) + w0a + t*w1a,  M[i][j] = <Ue_i, G_j>
                        float dM = hsum2(sub2(dotp(&UeP[i*4], &T[j*4]), dotp(&UeP[j*4], &T[i*4])));
                        float w0, w1; unp2(w01[TRI(i,j)], w0, w1);
                        fv[TRI(i,j)] = fmaf(t, w1, fmaf(0.5f, dM, w0));
                    }
                }
                kl = 0.5f * (hsum2(s1p) + hsum2(s2p));
            }

            // ===== phase 2: T <- vel rows (overwrites G in place) =====
            #pragma unroll
            for (int i = 0; i < 8; i++) {
                ull acc[4];
                #pragma unroll
                for (int j = 0; j < 8; j++) {
                    if (j == i) continue;
                    const bool first = (j == ((i == 0) ? 1 : 0));
                    float f = (i < j) ? fv[TRI(i,j)] : -fv[TRI(j,i)];
                    ull fd = dup_f(f);
                    #pragma unroll
                    for (int c = 0; c < 4; c++) {
                        if (first) acc[c] = mul2(fd, UeP[j*4+c]);
                        else       acc[c] = fma2(fd, UeP[j*4+c], acc[c]);
                    }
                }
                #pragma unroll
                for (int c = 0; c < 4; c++) T[i*4+c] = acc[c];
            }

            // ===== RK4 stage update (T = vel) =====
            if (s == 0) {
                lacc = kl;
                const ull hdt = dup_f(0.5f*DT);
                #pragma unroll
                for (int c = 0; c < 32; c++) {
                    sac[c*NT] = T[c];
                    UeP[c] = fma2(hdt, T[c], UeP[c]);     // UeP was U base
                }
            } else if (s == 1) {
                lacc = fmaf(2.0f, kl, lacc);
                const ull two = dup_f(2.0f), hdt = dup_f(0.5f*DT);
                #pragma unroll
                for (int c = 0; c < 32; c++) {
                    sac[c*NT] = fma2(two, T[c], sac[c*NT]);
                    UeP[c] = fma2(hdt, T[c], sub[c*NT]);
                }
            } else if (s == 2) {
                lacc = fmaf(2.0f, kl, lacc);
                const ull two = dup_f(2.0f), fdt = dup_f(DT);
                #pragma unroll
                for (int c = 0; c < 32; c++) {
                    sac[c*NT] = fma2(two, T[c], sac[c*NT]);
                    UeP[c] = fma2(fdt, T[c], sub[c*NT]);
                }
            } else {
                logj = fmaf(DT/6.0f, lacc + kl, logj);
                const ull d6 = dup_f(DT/6.0f);
                #pragma unroll
                for (int c = 0; c < 32; c++) {
                    ull un = fma2(d6, add2(sac[c*NT], T[c]), sub[c*NT]);
                    UeP[c] = un;
                    sub[c*NT] = un;
                }
            }
        }
    }

    // ---- write outputs: U then logj ----
    {
        ulonglong2* o2 = (ulonglong2*)(out + (size_t)gtid * 64);
        #pragma unroll
        for (int e = 0; e < 16; e++) {
            ulonglong2 w;
            w.x = UeP[2*e]; w.y = UeP[2*e+1];
            o2[e] = w;
        }
        out[(size_t)B * 64 + gtid] = logj;
    }
}

extern "C" void kernel_launch(void* const* d_in, const int* in_sizes, int n_in,
                              void* d_out, int out_size)
{
    const float* U0  = (const float*)d_in[0];
    const float* eps = (const float*)d_in[1];
    const float* W0  = (const float*)d_in[2];
    const float* W1  = (const float*)d_in[3];
    const float* W2  = (const float*)d_in[4];
    float* out = (float*)d_out;

    int B = in_sizes[0] / 64;
    size_t shmem = (size_t)(64 + 4 * 32 * NT) * sizeof(ull);   // ~192.6 KB
    cudaFuncSetAttribute(adj_lie_kernel,
                         cudaFuncAttributeMaxDynamicSharedMemorySize, (int)shmem);
    int grid = (B + NT - 1) / NT;
    adj_lie_kernel<<<grid, NT, shmem>>>(U0, eps, W0, W1, W2, out, B);
}

// round 10
// speedup vs baseline: 1.4074x; 1.4074x over previous
#include <cuda_runtime.h>

typedef unsigned long long ull;

#define NT 192
#define NSTEPS 16
#define DT (1.0f/16.0f)
// upper-triangle index for i<j, 8x8
#define TRI(i,j) ((i)*7 - (i)*((i)-1)/2 + (j) - (i) - 1)

__device__ __forceinline__ ull fma2(ull a, ull b, ull c){
    ull d; asm("fma.rn.f32x2 %0,%1,%2,%3;" : "=l"(d) : "l"(a),"l"(b),"l"(c)); return d;
}
__device__ __forceinline__ ull mul2(ull a, ull b){
    ull d; asm("mul.rn.f32x2 %0,%1,%2;" : "=l"(d) : "l"(a),"l"(b)); return d;
}
__device__ __forceinline__ ull add2(ull a, ull b){
    ull d; asm("add.rn.f32x2 %0,%1,%2;" : "=l"(d) : "l"(a),"l"(b)); return d;
}
__device__ __forceinline__ ull sub2(ull a, ull b){
    ull d; asm("sub.rn.f32x2 %0,%1,%2;" : "=l"(d) : "l"(a),"l"(b)); return d;
}
__device__ __forceinline__ float hsum2(ull a){
    float lo,hi; asm("mov.b64 {%0,%1},%2;" : "=f"(lo),"=f"(hi) : "l"(a)); return lo+hi;
}
__device__ __forceinline__ ull dup_f(float x){
    ull r; asm("mov.b64 %0,{%1,%1};" : "=l"(r) : "f"(x)); return r;
}
__device__ __forceinline__ ull dup_lo(ull a){
    ull r; asm("{.reg .f32 l,h; mov.b64 {l,h},%1; mov.b64 %0,{l,l};}" : "=l"(r) : "l"(a)); return r;
}
__device__ __forceinline__ ull dup_hi(ull a){
    ull r; asm("{.reg .f32 l,h; mov.b64 {l,h},%1; mov.b64 %0,{h,h};}" : "=l"(r) : "l"(a)); return r;
}
__device__ __forceinline__ ull pack2(float lo, float hi){
    ull r; asm("mov.b64 %0,{%1,%2};" : "=l"(r) : "f"(lo),"f"(hi)); return r;
}
__device__ __forceinline__ void unp2(ull a, float& lo, float& hi){
    asm("mov.b64 {%0,%1},%2;" : "=f"(lo),"=f"(hi) : "l"(a));
}
// packed dot of two 8-float rows (4 ull each): returns packed partial sums
__device__ __forceinline__ ull dotp(const ull* a, const ull* b){
    ull s = mul2(a[0],b[0]);
    s = fma2(a[1],b[1],s);
    s = fma2(a[2],b[2],s);
    s = fma2(a[3],b[3],s);
    return s;
}

extern "C" __global__ void __launch_bounds__(NT, 1)
adj_lie_kernel(const float* __restrict__ U0, const float* __restrict__ eps,
               const float* __restrict__ W0, const float* __restrict__ W1,
               const float* __restrict__ W2, float* __restrict__ out, int B)
{
    // W2a = W2 - W2^T (antisym). Only W2a ever enters the dynamics:
    //   F = w0a + t*w1a + 0.5*U*W2a*U^T       (product is antisymmetric)
    //   logj_rate = 0.5*Sum_{i<j} r_ij*(<hv_i,Ue_j> - <hv_j,Ue_i>),  hv = v*W2a (const)
    extern __shared__ ull shl[];
    ull* w2ac = shl;            // 32 : W2a column-packed: [k*4+c] = (W2a[2c][k], W2a[2c+1][k])
    ull* w2ar = shl + 32;       // 32 : W2a row-packed:    [k*4+c] = (W2a[k][2c], W2a[k][2c+1])
    ull* w01  = shl + 64;       // 28 : (w0a_ij, w1a_ij) per TRI pair
    ull* svb  = shl + 96;               // [32][NT] : v (eps) rows packed
    ull* shvb = svb  + 32*NT;           // [32][NT] : hv = v*W2a rows packed
    ull* subb = shvb + 32*NT;           // [32][NT] : U base
    ull* sacb = subb + 32*NT;           // [32][NT] : RK4 accumulator

    const int tid  = threadIdx.x;
    const int gtid = blockIdx.x * NT + tid;

    if (tid < 32) {
        int k = tid >> 2, c = tid & 3;
        float a0 = W2[(2*c  )*8 + k] - W2[k*8 + (2*c  )];   // W2a[2c  ][k]
        float a1 = W2[(2*c+1)*8 + k] - W2[k*8 + (2*c+1)];   // W2a[2c+1][k]
        w2ac[tid] = pack2(a0, a1);
        w2ar[tid] = pack2(-a0, -a1);                         // W2a[k][2c..2c+1]
    }
    if (tid < 64) {
        int i = tid >> 3, j = tid & 7;
        if (i < j) {
            w01[TRI(i,j)] = pack2(0.5f * (W0[i*8+j] - W0[j*8+i]),
                                  0.5f * (W1[i*8+j] - W1[j*8+i]));
        }
    }
    __syncthreads();

    if (gtid >= B) return;

    ull* sv  = svb  + tid;
    ull* shv = shvb + tid;
    ull* sub = subb + tid;
    ull* sac = sacb + tid;

    // ---- load U0 (regs + shared base) ----
    ull UeP[32];
    {
        const ulonglong2* u2 = (const ulonglong2*)(U0 + (size_t)gtid * 64);
        #pragma unroll
        for (int e = 0; e < 16; e++) {
            ulonglong2 u = u2[e];
            UeP[2*e] = u.x; UeP[2*e+1] = u.y;
        }
        #pragma unroll
        for (int c = 0; c < 32; c++) sub[c*NT] = UeP[c];
    }

    // ---- load eps: store v rows, and hv_i = v_i * W2a (constant over integration) ----
    {
        const ulonglong2* e2 = (const ulonglong2*)(eps + (size_t)gtid * 64);
        #pragma unroll
        for (int i = 0; i < 8; i++) {
            ulonglong2 a = e2[2*i], b = e2[2*i+1];
            ull vr[4] = {a.x, a.y, b.x, b.y};
            #pragma unroll
            for (int c = 0; c < 4; c++) sv[(i*4+c)*NT] = vr[c];
            ull acc[4];
            #pragma unroll
            for (int k = 0; k < 8; k++) {
                ull d = (k & 1) ? dup_hi(vr[k>>1]) : dup_lo(vr[k>>1]);
                #pragma unroll
                for (int c = 0; c < 4; c++)
                    acc[c] = (k == 0) ? mul2(d, w2ar[c]) : fma2(d, w2ar[k*4+c], acc[c]);
            }
            #pragma unroll
            for (int c = 0; c < 4; c++) shv[(i*4+c)*NT] = acc[c];
        }
    }

    float logj = 0.0f, lacc = 0.0f;

    #pragma unroll 1
    for (int step = 0; step < NSTEPS; step++) {
        float t0 = (float)step * DT;
        #pragma unroll 1
        for (int s = 0; s < 4; s++) {
            float t = t0 + ((s == 0) ? 0.0f : (s == 3 ? DT : 0.5f*DT));

            float kl;
            float fv[28];
            ull T[32];   // phase 1: Ga_j = W2a*Ue_j^T ; phase 2: vel rows (reuse)

            // ===== phase 1a: T = Ga =====
            #pragma unroll
            for (int j = 0; j < 8; j++) {
                #pragma unroll
                for (int k = 0; k < 8; k++) {
                    ull d = (k & 1) ? dup_hi(UeP[j*4+(k>>1)]) : dup_lo(UeP[j*4+(k>>1)]);
                    #pragma unroll
                    for (int c = 0; c < 4; c++)
                        T[j*4+c] = (k == 0) ? mul2(d, w2ac[c])
                                            : fma2(d, w2ac[k*4+c], T[j*4+c]);
                }
            }

            // ===== phase 1b: fused pair loop: r, kl, f =====
            {
                ull klp = 0ull;
                #pragma unroll
                for (int i = 0; i < 7; i++) {
                    ull vi[4], hvi[4];
                    #pragma unroll
                    for (int c = 0; c < 4; c++) { vi[c] = sv[(i*4+c)*NT]; hvi[c] = shv[(i*4+c)*NT]; }
                    #pragma unroll
                    for (int j = i+1; j < 8; j++) {
                        ull vj[4], hvj[4];
                        #pragma unroll
                        for (int c = 0; c < 4; c++) { vj[c] = sv[(j*4+c)*NT]; hvj[c] = shv[(j*4+c)*NT]; }

                        // r = <Ue_j, v_i> - <Ue_i, v_j>   (= 2*R_ij)
                        float r = hsum2(sub2(dotp(&UeP[j*4], vi), dotp(&UeP[i*4], vj)));
                        // qd = <hv_i, Ue_j> - <hv_j, Ue_i>   (packed partials)
                        ull qd = sub2(dotp(hvi, &UeP[j*4]), dotp(hvj, &UeP[i*4]));
                        klp = fma2(dup_f(r), qd, klp);
                        // f = w0a + t*w1a + 0.5*<Ue_i, Ga_j>
                        float g = hsum2(dotp(&UeP[i*4], &T[j*4]));
                        float w0, w1; unp2(w01[TRI(i,j)], w0, w1);
                        fv[TRI(i,j)] = fmaf(t, w1, fmaf(0.5f, g, w0));
                    }
                }
                // rate = 0.5 * Sum r*qd   (R = r/2, qd carries the other factor)
                kl = 0.5f * hsum2(klp);
            }

            // ===== phase 2: T <- vel rows (overwrites Ga in place) =====
            #pragma unroll
            for (int i = 0; i < 8; i++) {
                ull acc[4];
                #pragma unroll
                for (int j = 0; j < 8; j++) {
                    if (j == i) continue;
                    const bool first = (j == ((i == 0) ? 1 : 0));
                    float f = (i < j) ? fv[TRI(i,j)] : -fv[TRI(j,i)];
                    ull fd = dup_f(f);
                    #pragma unroll
                    for (int c = 0; c < 4; c++) {
                        if (first) acc[c] = mul2(fd, UeP[j*4+c]);
                        else       acc[c] = fma2(fd, UeP[j*4+c], acc[c]);
                    }
                }
                #pragma unroll
                for (int c = 0; c < 4; c++) T[i*4+c] = acc[c];
            }

            // ===== RK4 stage update (T = vel) =====
            if (s == 0) {
                lacc = kl;
                const ull hdt = dup_f(0.5f*DT);
                #pragma unroll
                for (int c = 0; c < 32; c++) {
                    sac[c*NT] = T[c];
                    UeP[c] = fma2(hdt, T[c], UeP[c]);     // UeP was U base
                }
            } else if (s == 1) {
                lacc = fmaf(2.0f, kl, lacc);
                const ull two = dup_f(2.0f), hdt = dup_f(0.5f*DT);
                #pragma unroll
                for (int c = 0; c < 32; c++) {
                    sac[c*NT] = fma2(two, T[c], sac[c*NT]);
                    UeP[c] = fma2(hdt, T[c], sub[c*NT]);
                }
            } else if (s == 2) {
                lacc = fmaf(2.0f, kl, lacc);
                const ull two = dup_f(2.0f), fdt = dup_f(DT);
                #pragma unroll
                for (int c = 0; c < 32; c++) {
                    sac[c*NT] = fma2(two, T[c], sac[c*NT]);
                    UeP[c] = fma2(fdt, T[c], sub[c*NT]);
                }
            } else {
                logj = fmaf(DT/6.0f, lacc + kl, logj);
                const ull d6 = dup_f(DT/6.0f);
                #pragma unroll
                for (int c = 0; c < 32; c++) {
                    ull un = fma2(d6, add2(sac[c*NT], T[c]), sub[c*NT]);
                    UeP[c] = un;
                    sub[c*NT] = un;
                }
            }
        }
    }

    // ---- write outputs: U then logj ----
    {
        ulonglong2* o2 = (ulonglong2*)(out + (size_t)gtid * 64);
        #pragma unroll
        for (int e = 0; e < 16; e++) {
            ulonglong2 w;
            w.x = UeP[2*e]; w.y = UeP[2*e+1];
            o2[e] = w;
        }
        out[(size_t)B * 64 + gtid] = logj;
    }
}

extern "C" void kernel_launch(void* const* d_in, const int* in_sizes, int n_in,
                              void* d_out, int out_size)
{
    const float* U0  = (const float*)d_in[0];
    const float* eps = (const float*)d_in[1];
    const float* W0  = (const float*)d_in[2];
    const float* W1  = (const float*)d_in[3];
    const float* W2  = (const float*)d_in[4];
    float* out = (float*)d_out;

    int B = in_sizes[0] / 64;
    size_t shmem = (size_t)(96 + 4 * 32 * NT) * sizeof(ull);   // ~192.8 KB
    cudaFuncSetAttribute(adj_lie_kernel,
                         cudaFuncAttributeMaxDynamicSharedMemorySize, (int)shmem);
    int grid = (B + NT - 1) / NT;
    adj_lie_kernel<<<grid, NT, shmem>>>(U0, eps, W0, W1, W2, out, B);
}

// round 11
// speedup vs baseline: 1.6894x; 1.2003x over previous
#include <cuda_runtime.h>

typedef unsigned long long ull;

#define NT 256
#define NSTEPS 16
#define DT (1.0f/16.0f)
// upper-triangle index for i<j, 8x8
#define TRI(i,j) ((i)*7 - (i)*((i)-1)/2 + (j) - (i) - 1)

__device__ __forceinline__ ull fma2(ull a, ull b, ull c){
    ull d; asm("fma.rn.f32x2 %0,%1,%2,%3;" : "=l"(d) : "l"(a),"l"(b),"l"(c)); return d;
}
__device__ __forceinline__ ull mul2(ull a, ull b){
    ull d; asm("mul.rn.f32x2 %0,%1,%2;" : "=l"(d) : "l"(a),"l"(b)); return d;
}
__device__ __forceinline__ ull add2(ull a, ull b){
    ull d; asm("add.rn.f32x2 %0,%1,%2;" : "=l"(d) : "l"(a),"l"(b)); return d;
}
__device__ __forceinline__ ull sub2(ull a, ull b){
    ull d; asm("sub.rn.f32x2 %0,%1,%2;" : "=l"(d) : "l"(a),"l"(b)); return d;
}
__device__ __forceinline__ float hsum2(ull a){
    float lo,hi; asm("mov.b64 {%0,%1},%2;" : "=f"(lo),"=f"(hi) : "l"(a)); return lo+hi;
}
__device__ __forceinline__ ull dup_f(float x){
    ull r; asm("mov.b64 %0,{%1,%1};" : "=l"(r) : "f"(x)); return r;
}
__device__ __forceinline__ ull dup_lo(ull a){
    ull r; asm("{.reg .f32 l,h; mov.b64 {l,h},%1; mov.b64 %0,{l,l};}" : "=l"(r) : "l"(a)); return r;
}
__device__ __forceinline__ ull dup_hi(ull a){
    ull r; asm("{.reg .f32 l,h; mov.b64 {l,h},%1; mov.b64 %0,{h,h};}" : "=l"(r) : "l"(a)); return r;
}
__device__ __forceinline__ ull pack2(float lo, float hi){
    ull r; asm("mov.b64 %0,{%1,%2};" : "=l"(r) : "f"(lo),"f"(hi)); return r;
}
__device__ __forceinline__ void unp2(ull a, float& lo, float& hi){
    asm("mov.b64 {%0,%1},%2;" : "=f"(lo),"=f"(hi) : "l"(a));
}
// packed dot of two 8-float rows (4 ull each): returns packed partial sums
__device__ __forceinline__ ull dotp(const ull* a, const ull* b){
    ull s = mul2(a[0],b[0]);
    s = fma2(a[1],b[1],s);
    s = fma2(a[2],b[2],s);
    s = fma2(a[3],b[3],s);
    return s;
}

extern "C" __global__ void __launch_bounds__(NT, 1)
adj_lie_kernel(const float* __restrict__ U0, const float* __restrict__ eps,
               const float* __restrict__ W0, const float* __restrict__ W1,
               const float* __restrict__ W2, float* __restrict__ out, int B)
{
    // W2a = W2 - W2^T. Dynamics:
    //   F = w0a + t*w1a + 0.5*U*W2a*U^T        (product is antisymmetric)
    //   logj_rate = 0.5 * Sum_i <v_i, y_i>,  y_i = W2a*z_i^T,  z_i = Sum_j r_ij Ue_j
    //   r_ij = <Ue_j, v_i> - <Ue_i, v_j>  (antisym, r_ii = 0)
    extern __shared__ ull shl[];
    ull* w2ac = shl;            // 32 : W2a column-packed: [k*4+c] = (W2a[2c][k], W2a[2c+1][k])
    ull* w01  = shl + 32;       // 28 : (w0a_ij, w1a_ij) per TRI pair
    ull* svb  = shl + 64;               // [32][NT] : v (eps) rows packed
    ull* subb = svb  + 32*NT;           // [32][NT] : U base
    ull* sacb = subb + 32*NT;           // [32][NT] : RK4 accumulator

    const int tid  = threadIdx.x;
    const int gtid = blockIdx.x * NT + tid;

    if (tid < 32) {
        int k = tid >> 2, c = tid & 3;
        float a0 = W2[(2*c  )*8 + k] - W2[k*8 + (2*c  )];   // W2a[2c  ][k]
        float a1 = W2[(2*c+1)*8 + k] - W2[k*8 + (2*c+1)];   // W2a[2c+1][k]
        w2ac[tid] = pack2(a0, a1);
    }
    if (tid < 64) {
        int i = tid >> 3, j = tid & 7;
        if (i < j) {
            w01[TRI(i,j)] = pack2(0.5f * (W0[i*8+j] - W0[j*8+i]),
                                  0.5f * (W1[i*8+j] - W1[j*8+i]));
        }
    }
    __syncthreads();

    if (gtid >= B) return;

    ull* sv  = svb  + tid;
    ull* sub = subb + tid;
    ull* sac = sacb + tid;

    // ---- load U0 (regs + shared base), eps -> shared ----
    ull UeP[32];
    {
        const ulonglong2* u2 = (const ulonglong2*)(U0  + (size_t)gtid * 64);
        const ulonglong2* e2 = (const ulonglong2*)(eps + (size_t)gtid * 64);
        #pragma unroll
        for (int e = 0; e < 16; e++) {
            ulonglong2 u = u2[e];
            UeP[2*e] = u.x; UeP[2*e+1] = u.y;
            ulonglong2 v = e2[e];
            sv[(2*e)*NT] = v.x; sv[(2*e+1)*NT] = v.y;
        }
        #pragma unroll
        for (int c = 0; c < 32; c++) sub[c*NT] = UeP[c];
    }

    float logj = 0.0f, lacc = 0.0f;

    #pragma unroll 1
    for (int step = 0; step < NSTEPS; step++) {
        float t0 = (float)step * DT;
        #pragma unroll 1
        for (int s = 0; s < 4; s++) {
            float t = t0 + ((s == 0) ? 0.0f : (s == 3 ? DT : 0.5f*DT));

            float kl;
            float rv[28];
            float fv[28];
            ull T[32];   // phase 1: Ga_j = W2a*Ue_j^T ; phase 2: vel rows (reuse)

            // ===== phase 1a: T = Ga =====
            #pragma unroll
            for (int j = 0; j < 8; j++) {
                #pragma unroll
                for (int k = 0; k < 8; k++) {
                    ull d = (k & 1) ? dup_hi(UeP[j*4+(k>>1)]) : dup_lo(UeP[j*4+(k>>1)]);
                    #pragma unroll
                    for (int c = 0; c < 4; c++)
                        T[j*4+c] = (k == 0) ? mul2(d, w2ac[c])
                                            : fma2(d, w2ac[k*4+c], T[j*4+c]);
                }
            }

            // ===== phase 1b: pair loop: r_ij and f_ij =====
            #pragma unroll
            for (int i = 0; i < 7; i++) {
                ull vi[4];
                #pragma unroll
                for (int c = 0; c < 4; c++) vi[c] = sv[(i*4+c)*NT];
                #pragma unroll
                for (int j = i+1; j < 8; j++) {
                    ull vj[4];
                    #pragma unroll
                    for (int c = 0; c < 4; c++) vj[c] = sv[(j*4+c)*NT];
                    // r = <Ue_j, v_i> - <Ue_i, v_j>
                    rv[TRI(i,j)] = hsum2(sub2(dotp(&UeP[j*4], vi), dotp(&UeP[i*4], vj)));
                    // f = w0a + t*w1a + 0.5*<Ue_i, Ga_j>
                    float g = hsum2(dotp(&UeP[i*4], &T[j*4]));
                    float w0, w1; unp2(w01[TRI(i,j)], w0, w1);
                    fv[TRI(i,j)] = fmaf(t, w1, fmaf(0.5f, g, w0));
                }
            }

            // ===== phase 1c: kl = 0.5 * Sum_i <v_i, W2a*(Sum_j r_ij Ue_j)^T> =====
            {
                ull klp = 0ull;
                #pragma unroll
                for (int i = 0; i < 8; i++) {
                    // z = Sum_{j != i} r_ij * Ue_j
                    ull z[4];
                    #pragma unroll
                    for (int j = 0; j < 8; j++) {
                        if (j == i) continue;
                        const bool first = (j == ((i == 0) ? 1 : 0));
                        float r = (i < j) ? rv[TRI(i,j)] : -rv[TRI(j,i)];
                        ull rd = dup_f(r);
                        #pragma unroll
                        for (int c = 0; c < 4; c++) {
                            if (first) z[c] = mul2(rd, UeP[j*4+c]);
                            else       z[c] = fma2(rd, UeP[j*4+c], z[c]);
                        }
                    }
                    // y = W2a * z^T  (same broadcast pattern as Ga)
                    ull y[4];
                    #pragma unroll
                    for (int k = 0; k < 8; k++) {
                        ull d = (k & 1) ? dup_hi(z[k>>1]) : dup_lo(z[k>>1]);
                        #pragma unroll
                        for (int c = 0; c < 4; c++)
                            y[c] = (k == 0) ? mul2(d, w2ac[c]) : fma2(d, w2ac[k*4+c], y[c]);
                    }
                    // klp += <v_i, y>  (packed partials)
                    ull vi[4];
                    #pragma unroll
                    for (int c = 0; c < 4; c++) vi[c] = sv[(i*4+c)*NT];
                    klp = add2(klp, dotp(vi, y));
                }
                kl = 0.5f * hsum2(klp);
            }

            // ===== phase 2: T <- vel rows (overwrites Ga in place) =====
            #pragma unroll
            for (int i = 0; i < 8; i++) {
                ull acc[4];
                #pragma unroll
                for (int j = 0; j < 8; j++) {
                    if (j == i) continue;
                    const bool first = (j == ((i == 0) ? 1 : 0));
                    float f = (i < j) ? fv[TRI(i,j)] : -fv[TRI(j,i)];
                    ull fd = dup_f(f);
                    #pragma unroll
                    for (int c = 0; c < 4; c++) {
                        if (first) acc[c] = mul2(fd, UeP[j*4+c]);
                        else       acc[c] = fma2(fd, UeP[j*4+c], acc[c]);
                    }
                }
                #pragma unroll
                for (int c = 0; c < 4; c++) T[i*4+c] = acc[c];
            }

            // ===== RK4 stage update (T = vel) =====
            if (s == 0) {
                lacc = kl;
                const ull hdt = dup_f(0.5f*DT);
                #pragma unroll
                for (int c = 0; c < 32; c++) {
                    sac[c*NT] = T[c];
                    UeP[c] = fma2(hdt, T[c], UeP[c]);     // UeP was U base
                }
            } else if (s == 1) {
                lacc = fmaf(2.0f, kl, lacc);
                const ull two = dup_f(2.0f), hdt = dup_f(0.5f*DT);
                #pragma unroll
                for (int c = 0; c < 32; c++) {
                    sac[c*NT] = fma2(two, T[c], sac[c*NT]);
                    UeP[c] = fma2(hdt, T[c], sub[c*NT]);
                }
            } else if (s == 2) {
                lacc = fmaf(2.0f, kl, lacc);
                const ull two = dup_f(2.0f), fdt = dup_f(DT);
                #pragma unroll
                for (int c = 0; c < 32; c++) {
                    sac[c*NT] = fma2(two, T[c], sac[c*NT]);
                    UeP[c] = fma2(fdt, T[c], sub[c*NT]);
                }
            } else {
                logj = fmaf(DT/6.0f, lacc + kl, logj);
                const ull d6 = dup_f(DT/6.0f);
                #pragma unroll
                for (int c = 0; c < 32; c++) {
                    ull un = fma2(d6, add2(sac[c*NT], T[c]), sub[c*NT]);
                    UeP[c] = un;
                    sub[c*NT] = un;
                }
            }
        }
    }

    // ---- write outputs: U then logj ----
    {
        ulonglong2* o2 = (ulonglong2*)(out + (size_t)gtid * 64);
        #pragma unroll
        for (int e = 0; e < 16; e++) {
            ulonglong2 w;
            w.x = UeP[2*e]; w.y = UeP[2*e+1];
            o2[e] = w;
        }
        out[(size_t)B * 64 + gtid] = logj;
    }
}

extern "C" void kernel_launch(void* const* d_in, const int* in_sizes, int n_in,
                              void* d_out, int out_size)
{
    const float* U0  = (const float*)d_in[0];
    const float* eps = (const float*)d_in[1];
    const float* W0  = (const float*)d_in[2];
    const float* W1  = (const float*)d_in[3];
    const float* W2  = (const float*)d_in[4];
    float* out = (float*)d_out;

    int B = in_sizes[0] / 64;
    size_t shmem = (size_t)(64 + 3 * 32 * NT) * sizeof(ull);   // ~192.5 KB
    cudaFuncSetAttribute(adj_lie_kernel,
                         cudaFuncAttributeMaxDynamicSharedMemorySize, (int)shmem);
    int grid = (B + NT - 1) / NT;
    adj_lie_kernel<<<grid, NT, shmem>>>(U0, eps, W0, W1, W2, out, B);
}